// round 6
// baseline (speedup 1.0000x reference)
#include <cuda_runtime.h>
#include <cuda_fp16.h>
#include <cstdint>
#include <math.h>

#define NMAT 4096
#define INF  1024
#define OUTF 1024
#define NB   8
#define K1   9216              // total K (1024*9), single fp16 pass
#define KTILE 32
#define KTILES (K1 / KTILE)    // 288
#define BM 64
#define BN 64
#define STAGES 3

// padded smem row: 32 fp16 + 8 pad = 40 elems = 80 bytes
#define ROWB 80
#define A_BYTES (BM * ROWB)    // 5120
#define B_BYTES (BN * ROWB)    // 5120
#define STAGE_BYTES (A_BYTES + B_BYTES)       // 10240
#define SMEM_TOTAL (STAGES * STAGE_BYTES)     // 30720

// ---------------- scratch (__device__ globals; no allocs allowed) ----------
__device__ __align__(128) __half g_A[(size_t)NMAT * K1];   // [4096, 9216] fp16
__device__ __align__(128) __half g_W[(size_t)OUTF * K1];   // [1024, 9216] fp16

// ---------------- PTX helpers (family-portable only) ------------------------
__device__ __forceinline__ uint32_t smem_u32(const void* p) {
    uint32_t a;
    asm("{ .reg .u64 t; cvta.to.shared.u64 t, %1; cvt.u32.u64 %0, t; }" : "=r"(a) : "l"(p));
    return a;
}
__device__ __forceinline__ void cp_async16(uint32_t dst, const void* src) {
    asm volatile("cp.async.cg.shared.global [%0], [%1], 16;" :: "r"(dst), "l"(src) : "memory");
}
__device__ __forceinline__ void cp_commit() {
    asm volatile("cp.async.commit_group;" ::: "memory");
}
template <int N>
__device__ __forceinline__ void cp_wait() {
    asm volatile("cp.async.wait_group %0;" :: "n"(N) : "memory");
}
__device__ __forceinline__ void ldsm_x4(uint32_t& r0, uint32_t& r1, uint32_t& r2,
                                        uint32_t& r3, uint32_t addr) {
    asm volatile("ldmatrix.sync.aligned.m8n8.x4.shared.b16 {%0,%1,%2,%3}, [%4];"
                 : "=r"(r0), "=r"(r1), "=r"(r2), "=r"(r3) : "r"(addr));
}
// NON-trans: B tile is n-major (row=n, col=k); fragment pair must vary over k.
__device__ __forceinline__ void ldsm_x2(uint32_t& r0, uint32_t& r1, uint32_t addr) {
    asm volatile("ldmatrix.sync.aligned.m8n8.x2.shared.b16 {%0,%1}, [%2];"
                 : "=r"(r0), "=r"(r1) : "r"(addr));
}
__device__ __forceinline__ void mma_f16(float& c0, float& c1, float& c2, float& c3,
                                        uint32_t a0, uint32_t a1, uint32_t a2, uint32_t a3,
                                        uint32_t b0, uint32_t b1) {
    asm volatile("mma.sync.aligned.m16n8k16.row.col.f32.f16.f16.f32 "
                 "{%0,%1,%2,%3}, {%4,%5,%6,%7}, {%8,%9}, {%0,%1,%2,%3};"
                 : "+f"(c0), "+f"(c1), "+f"(c2), "+f"(c3)
                 : "r"(a0), "r"(a1), "r"(a2), "r"(a3), "r"(b0), "r"(b1));
}

// ===========================================================================
// Stage 1: A = fp16 of [silu(x) | bspline basis], K map k = slot*1024 + i
// ===========================================================================
__global__ void build_A_kernel(const float* __restrict__ x) {
    int idx = blockIdx.x * blockDim.x + threadIdx.x;
    if (idx >= NMAT * INF) return;
    float v = x[idx];

    float vals[9];
    vals[0] = v / (1.0f + __expf(-v));   // SiLU (fast exp; rounded to fp16 anyway)

    const float h = 0.4f, lo = -1.0f;
    float b[11];
#pragma unroll
    for (int j = 0; j < 11; j++) {
        float t0 = (float)(j - 3) * h + lo;
        float t1 = (float)(j - 2) * h + lo;
        b[j] = (v >= t0 && v < t1) ? 1.0f : 0.0f;
    }
#pragma unroll
    for (int k = 1; k <= 3; k++) {
        float inv = 1.0f / ((float)k * h + 1e-8f);
#pragma unroll
        for (int j = 0; j + k < 11; j++) {
            float tj   = (float)(j - 3) * h + lo;
            float tjk1 = (float)(j + k - 2) * h + lo;
            b[j] = (v - tj) * inv * b[j] + (tjk1 - v) * inv * b[j + 1];
        }
    }
#pragma unroll
    for (int j = 0; j < NB; j++) vals[1 + j] = b[j];

    size_t rb = (size_t)(idx >> 10) * K1 + (idx & 1023);
#pragma unroll
    for (int s = 0; s < 9; s++)
        g_A[rb + s * 1024] = __float2half_rn(vals[s]);
}

// ===========================================================================
// Stage 2: W = fp16 of [base_weight | spline_weight], same K map
// ===========================================================================
__global__ void pack_W_kernel(const float* __restrict__ bw,
                              const float* __restrict__ sw) {
    int idx = blockIdx.x * blockDim.x + threadIdx.x;   // o*1024 + i
    if (idx >= OUTF * INF) return;
    size_t rb = (size_t)(idx >> 10) * K1 + (idx & 1023);

    g_W[rb] = __float2half_rn(bw[idx]);
    const float4* s4 = (const float4*)(sw + (size_t)idx * NB);
    float4 s0 = s4[0], s1 = s4[1];
    g_W[rb + 1 * 1024] = __float2half_rn(s0.x);
    g_W[rb + 2 * 1024] = __float2half_rn(s0.y);
    g_W[rb + 3 * 1024] = __float2half_rn(s0.z);
    g_W[rb + 4 * 1024] = __float2half_rn(s0.w);
    g_W[rb + 5 * 1024] = __float2half_rn(s1.x);
    g_W[rb + 6 * 1024] = __float2half_rn(s1.y);
    g_W[rb + 7 * 1024] = __float2half_rn(s1.z);
    g_W[rb + 8 * 1024] = __float2half_rn(s1.w);
}

// ===========================================================================
// Stage 3: mma.sync fp16 GEMM, 64x64 tiles (fine-grained for wave balance)
// 4 warps, warp tile 32x32 (mt=2 of m16, nt=4 of n8)
// ===========================================================================
__device__ __forceinline__ void load_tile(uint32_t sbase, int kb, int bm, int bn, int tid) {
    size_t kof = (size_t)kb * KTILE;
    uint32_t sA = sbase;
    uint32_t sB = sbase + A_BYTES;
#pragma unroll
    for (int r = 0; r < 2; r++) {
        int ix = tid + r * 128;          // 256 chunks of 16B (64 rows x 4)
        int row = ix >> 2, c = ix & 3;
        cp_async16(sA + row * ROWB + c * 16,
                   g_A + ((size_t)(bm + row) * K1 + kof + c * 8));
    }
#pragma unroll
    for (int r = 0; r < 2; r++) {
        int ix = tid + r * 128;
        int row = ix >> 2, c = ix & 3;
        cp_async16(sB + row * ROWB + c * 16,
                   g_W + ((size_t)(bn + row) * K1 + kof + c * 8));
    }
}

__global__ void __launch_bounds__(128)
gemm_kernel(const float* __restrict__ bias, float* __restrict__ C) {
    extern __shared__ char smem[];
    uint32_t sb = smem_u32(smem);

    const int tid = threadIdx.x;
    const int wid = tid >> 5;
    const int lane = tid & 31;
    const int warp_m = wid & 1;        // 2 warp rows (32 m each)
    const int warp_n = wid >> 1;       // 2 warp cols (32 n each)
    const int bm = blockIdx.y * BM;
    const int bn = blockIdx.x * BN;

    float acc[2][4][4];                // [mt][nt][frag]
#pragma unroll
    for (int i = 0; i < 2; i++)
#pragma unroll
        for (int j = 0; j < 4; j++)
#pragma unroll
            for (int q = 0; q < 4; q++) acc[i][j][q] = 0.0f;

    // prefetch stages 0,1
    load_tile(sb + 0 * STAGE_BYTES, 0, bm, bn, tid); cp_commit();
    load_tile(sb + 1 * STAGE_BYTES, 1, bm, bn, tid); cp_commit();

    const int a_row = (lane & 15);
    const int a_kb  = ((lane >> 4) << 3) * 2;
    const int b_row = (lane & 7);
    const int b_kb  = (((lane >> 3) & 1) << 3) * 2;

    for (int kb = 0; kb < KTILES; kb++) {
        uint32_t st = sb + (kb % STAGES) * STAGE_BYTES;
        cp_wait<1>();
        __syncthreads();
        if (kb + 2 < KTILES)
            load_tile(sb + ((kb + 2) % STAGES) * STAGE_BYTES, kb + 2, bm, bn, tid);
        cp_commit();

        uint32_t sA = st;
        uint32_t sB = st + A_BYTES;
#pragma unroll
        for (int kk = 0; kk < 2; kk++) {
            int k0b = kk * 16 * 2;
            uint32_t a[2][4];
#pragma unroll
            for (int mt = 0; mt < 2; mt++) {
                int m0 = warp_m * 32 + mt * 16;
                ldsm_x4(a[mt][0], a[mt][1], a[mt][2], a[mt][3],
                        sA + (m0 + a_row) * ROWB + k0b + a_kb);
            }
            uint32_t bfr[4][2];
#pragma unroll
            for (int nt = 0; nt < 4; nt++) {
                int n0 = warp_n * 32 + nt * 8;
                ldsm_x2(bfr[nt][0], bfr[nt][1],
                        sB + (n0 + b_row) * ROWB + k0b + b_kb);
            }
#pragma unroll
            for (int mt = 0; mt < 2; mt++)
#pragma unroll
                for (int nt = 0; nt < 4; nt++)
                    mma_f16(acc[mt][nt][0], acc[mt][nt][1], acc[mt][nt][2], acc[mt][nt][3],
                            a[mt][0], a[mt][1], a[mt][2], a[mt][3],
                            bfr[nt][0], bfr[nt][1]);
        }
        __syncthreads();
    }

    // epilogue: bias + store
#pragma unroll
    for (int mt = 0; mt < 2; mt++) {
        int row0 = bm + warp_m * 32 + mt * 16 + (lane >> 2);
#pragma unroll
        for (int nt = 0; nt < 4; nt++) {
            int col = bn + warp_n * 32 + nt * 8 + (lane & 3) * 2;
            float b0 = __ldg(bias + col);
            float b1 = __ldg(bias + col + 1);
            float2 v0 = make_float2(acc[mt][nt][0] + b0, acc[mt][nt][1] + b1);
            float2 v1 = make_float2(acc[mt][nt][2] + b0, acc[mt][nt][3] + b1);
            *(float2*)(C + (size_t)row0 * OUTF + col)       = v0;
            *(float2*)(C + (size_t)(row0 + 8) * OUTF + col) = v1;
        }
    }
}

// ===========================================================================
extern "C" void kernel_launch(void* const* d_in, const int* in_sizes, int n_in,
                              void* d_out, int out_size) {
    const float* x    = (const float*)d_in[0];   // [4096,1024]
    const float* bw   = (const float*)d_in[1];   // [1024,1024]
    const float* bias = (const float*)d_in[2];   // [1024]
    const float* sw   = (const float*)d_in[3];   // [1024,1024,8]
    float* out = (float*)d_out;                  // [4096,1024]

    static bool attr_set = false;
    if (!attr_set) {
        cudaFuncSetAttribute(gemm_kernel,
                             cudaFuncAttributeMaxDynamicSharedMemorySize, SMEM_TOTAL);
        attr_set = true;
    }

    build_A_kernel<<<(NMAT * INF + 255) / 256, 256>>>(x);
    pack_W_kernel<<<(OUTF * INF + 255) / 256, 256>>>(bw, sw);

    dim3 grid(OUTF / BN, NMAT / BM);   // (16, 64) = 1024 CTAs
    gemm_kernel<<<grid, 128, SMEM_TOTAL>>>(bias, out);
}

// round 7
// speedup vs baseline: 1.1338x; 1.1338x over previous
#include <cuda_runtime.h>
#include <cuda_fp16.h>
#include <cstdint>
#include <math.h>

#define NMAT 4096
#define INF  1024
#define OUTF 1024
#define NB   8
#define K1   9216              // total K (1024*9), single fp16 pass
#define KTILE 32
#define KTILES (K1 / KTILE)    // 288
#define SPLITK 4
#define KT_PER (KTILES / SPLITK)   // 72
#define BM 128
#define BN 128
#define STAGES 3

// padded smem row: 32 fp16 + 8 pad = 40 elems = 80 bytes
#define ROWB 80
#define A_BYTES (BM * ROWB)
#define B_BYTES (BN * ROWB)
#define STAGE_BYTES (A_BYTES + B_BYTES)       // 20480
#define SMEM_TOTAL (STAGES * STAGE_BYTES)     // 61440

// ---------------- scratch (__device__ globals; no allocs allowed) ----------
__device__ __align__(128) __half g_A[(size_t)NMAT * K1];   // [4096, 9216] fp16
__device__ __align__(128) __half g_W[(size_t)OUTF * K1];   // [1024, 9216] fp16
__device__ unsigned g_cnt[256];                            // split-k tile counters

// ---------------- PTX helpers (family-portable only) ------------------------
__device__ __forceinline__ uint32_t smem_u32(const void* p) {
    uint32_t a;
    asm("{ .reg .u64 t; cvta.to.shared.u64 t, %1; cvt.u32.u64 %0, t; }" : "=r"(a) : "l"(p));
    return a;
}
__device__ __forceinline__ void cp_async16(uint32_t dst, const void* src) {
    asm volatile("cp.async.cg.shared.global [%0], [%1], 16;" :: "r"(dst), "l"(src) : "memory");
}
__device__ __forceinline__ void cp_commit() {
    asm volatile("cp.async.commit_group;" ::: "memory");
}
template <int N>
__device__ __forceinline__ void cp_wait() {
    asm volatile("cp.async.wait_group %0;" :: "n"(N) : "memory");
}
__device__ __forceinline__ void ldsm_x4(uint32_t& r0, uint32_t& r1, uint32_t& r2,
                                        uint32_t& r3, uint32_t addr) {
    asm volatile("ldmatrix.sync.aligned.m8n8.x4.shared.b16 {%0,%1,%2,%3}, [%4];"
                 : "=r"(r0), "=r"(r1), "=r"(r2), "=r"(r3) : "r"(addr));
}
// NON-trans: B tile is n-major (row=n, col=k); fragment pair must vary over k.
__device__ __forceinline__ void ldsm_x2(uint32_t& r0, uint32_t& r1, uint32_t addr) {
    asm volatile("ldmatrix.sync.aligned.m8n8.x2.shared.b16 {%0,%1}, [%2];"
                 : "=r"(r0), "=r"(r1) : "r"(addr));
}
__device__ __forceinline__ void mma_f16(float& c0, float& c1, float& c2, float& c3,
                                        uint32_t a0, uint32_t a1, uint32_t a2, uint32_t a3,
                                        uint32_t b0, uint32_t b1) {
    asm volatile("mma.sync.aligned.m16n8k16.row.col.f32.f16.f16.f32 "
                 "{%0,%1,%2,%3}, {%4,%5,%6,%7}, {%8,%9}, {%0,%1,%2,%3};"
                 : "+f"(c0), "+f"(c1), "+f"(c2), "+f"(c3)
                 : "r"(a0), "r"(a1), "r"(a2), "r"(a3), "r"(b0), "r"(b1));
}

// ===========================================================================
// Stage 1: A = fp16 of [silu(x) | bspline basis], K map k = slot*1024 + i.
// Closed-form uniform cubic B-spline (piecewise poly) instead of Cox-de Boor
// lattice: deviations ~1e-7 << fp16 ulp.
// ===========================================================================
__global__ void build_A_kernel(const float* __restrict__ x) {
    int idx = blockIdx.x * blockDim.x + threadIdx.x;
    if (idx >= NMAT * INF) return;
    float v = x[idx];

    float s = v / (1.0f + __expf(-v));   // SiLU

    // knot-relative coordinate: p = (v - t0)/h, t0 = -2.2, h = 0.4
    float p = (v + 2.2f) * 2.5f;
    float pf = floorf(p);
    int iv = (int)pf;
    float u = p - pf;
    bool inr = (p >= 0.0f) && (p < 11.0f);

    float u2 = u * u, u3 = u2 * u;
    const float i6 = 1.0f / 6.0f;
    // active basis values for j = iv-3 .. iv
    float c0 = (-u3 + 3.0f * u2 - 3.0f * u + 1.0f) * i6;   // j = iv-3
    float c1 = (3.0f * u3 - 6.0f * u2 + 4.0f) * i6;        // j = iv-2
    float c2 = (-3.0f * u3 + 3.0f * u2 + 3.0f * u + 1.0f) * i6; // j = iv-1
    float c3 = u3 * i6;                                    // j = iv

    size_t rb = (size_t)(idx >> 10) * K1 + (idx & 1023);
    g_A[rb] = __float2half_rn(s);
#pragma unroll
    for (int j = 0; j < NB; j++) {
        int d = iv - j;
        float val = (d == 0) ? c3 : (d == 1) ? c2 : (d == 2) ? c1 : (d == 3) ? c0 : 0.0f;
        val = inr ? val : 0.0f;
        g_A[rb + (j + 1) * 1024] = __float2half_rn(val);
    }
}

// ===========================================================================
// Stage 2: W = fp16 of [base_weight | spline_weight], same K map
// ===========================================================================
__global__ void pack_W_kernel(const float* __restrict__ bw,
                              const float* __restrict__ sw) {
    int idx = blockIdx.x * blockDim.x + threadIdx.x;   // o*1024 + i
    if (idx >= OUTF * INF) return;
    size_t rb = (size_t)(idx >> 10) * K1 + (idx & 1023);

    g_W[rb] = __float2half_rn(bw[idx]);
    const float4* s4 = (const float4*)(sw + (size_t)idx * NB);
    float4 s0 = s4[0], s1 = s4[1];
    g_W[rb + 1 * 1024] = __float2half_rn(s0.x);
    g_W[rb + 2 * 1024] = __float2half_rn(s0.y);
    g_W[rb + 3 * 1024] = __float2half_rn(s0.z);
    g_W[rb + 4 * 1024] = __float2half_rn(s0.w);
    g_W[rb + 5 * 1024] = __float2half_rn(s1.x);
    g_W[rb + 6 * 1024] = __float2half_rn(s1.y);
    g_W[rb + 7 * 1024] = __float2half_rn(s1.z);
    g_W[rb + 8 * 1024] = __float2half_rn(s1.w);
}

__global__ void reset_cnt_kernel() {
    g_cnt[threadIdx.x] = 0u;
}

// ===========================================================================
// Stage 3: mma.sync fp16 GEMM, 128x128 tiles, serial split-K (z = 4 strata)
// ===========================================================================
__device__ __forceinline__ void load_tile(uint32_t sbase, int kb, int bm, int bn, int tid) {
    size_t kof = (size_t)kb * KTILE;
    uint32_t sA = sbase;
    uint32_t sB = sbase + A_BYTES;
#pragma unroll
    for (int r = 0; r < 2; r++) {
        int ix = tid + r * 256;          // 512 chunks of 16B
        int row = ix >> 2, c = ix & 3;
        cp_async16(sA + row * ROWB + c * 16,
                   g_A + ((size_t)(bm + row) * K1 + kof + c * 8));
    }
#pragma unroll
    for (int r = 0; r < 2; r++) {
        int ix = tid + r * 256;
        int row = ix >> 2, c = ix & 3;
        cp_async16(sB + row * ROWB + c * 16,
                   g_W + ((size_t)(bn + row) * K1 + kof + c * 8));
    }
}

__global__ void __launch_bounds__(256, 2)
gemm_kernel(const float* __restrict__ bias, float* __restrict__ C) {
    extern __shared__ char smem[];
    uint32_t sb = smem_u32(smem);

    const int tid = threadIdx.x;
    const int wid = tid >> 5;
    const int lane = tid & 31;
    const int warp_m = wid & 1;        // 2 warps along M (64 each)
    const int warp_n = wid >> 1;       // 4 warps along N (32 each)
    const int bm = blockIdx.y * BM;
    const int bn = blockIdx.x * BN;
    const int kz = blockIdx.z;
    const int kb0 = kz * KT_PER;
    const int tile = blockIdx.y * gridDim.x + blockIdx.x;   // 0..255

    float acc[4][4][4];                // [mt][nt][frag]
#pragma unroll
    for (int i = 0; i < 4; i++)
#pragma unroll
        for (int j = 0; j < 4; j++)
#pragma unroll
            for (int q = 0; q < 4; q++) acc[i][j][q] = 0.0f;

    // prefetch stages 0,1
    load_tile(sb + 0 * STAGE_BYTES, kb0 + 0, bm, bn, tid); cp_commit();
    load_tile(sb + 1 * STAGE_BYTES, kb0 + 1, bm, bn, tid); cp_commit();

    const int a_row = (lane & 15);
    const int a_kb  = ((lane >> 4) << 3) * 2;
    const int b_row = (lane & 7);
    const int b_kb  = (((lane >> 3) & 1) << 3) * 2;

    for (int kb = 0; kb < KT_PER; kb++) {
        uint32_t st = sb + (kb % STAGES) * STAGE_BYTES;
        cp_wait<1>();
        __syncthreads();
        if (kb + 2 < KT_PER)
            load_tile(sb + ((kb + 2) % STAGES) * STAGE_BYTES, kb0 + kb + 2, bm, bn, tid);
        cp_commit();

        uint32_t sA = st;
        uint32_t sB = st + A_BYTES;
#pragma unroll
        for (int kk = 0; kk < 2; kk++) {
            int k0b = kk * 16 * 2;
            uint32_t a[4][4];
#pragma unroll
            for (int mt = 0; mt < 4; mt++) {
                int m0 = warp_m * 64 + mt * 16;
                ldsm_x4(a[mt][0], a[mt][1], a[mt][2], a[mt][3],
                        sA + (m0 + a_row) * ROWB + k0b + a_kb);
            }
            uint32_t bfr[4][2];
#pragma unroll
            for (int nt = 0; nt < 4; nt++) {
                int n0 = warp_n * 32 + nt * 8;
                ldsm_x2(bfr[nt][0], bfr[nt][1],
                        sB + (n0 + b_row) * ROWB + k0b + b_kb);
            }
#pragma unroll
            for (int mt = 0; mt < 4; mt++)
#pragma unroll
                for (int nt = 0; nt < 4; nt++)
                    mma_f16(acc[mt][nt][0], acc[mt][nt][1], acc[mt][nt][2], acc[mt][nt][3],
                            a[mt][0], a[mt][1], a[mt][2], a[mt][3],
                            bfr[nt][0], bfr[nt][1]);
        }
        __syncthreads();
    }

    // ---------------- serial split-K epilogue -----------------------------
    if (kz == 0) {
        // write C = acc + bias
#pragma unroll
        for (int mt = 0; mt < 4; mt++) {
            int row0 = bm + warp_m * 64 + mt * 16 + (lane >> 2);
#pragma unroll
            for (int nt = 0; nt < 4; nt++) {
                int col = bn + warp_n * 32 + nt * 8 + (lane & 3) * 2;
                float b0 = __ldg(bias + col);
                float b1 = __ldg(bias + col + 1);
                float2 v0 = make_float2(acc[mt][nt][0] + b0, acc[mt][nt][1] + b1);
                float2 v1 = make_float2(acc[mt][nt][2] + b0, acc[mt][nt][3] + b1);
                *(float2*)(C + (size_t)row0 * OUTF + col)       = v0;
                *(float2*)(C + (size_t)(row0 + 8) * OUTF + col) = v1;
            }
        }
        __threadfence();
        __syncthreads();
        if (tid == 0) atomicAdd(&g_cnt[tile], 1u);
    } else {
        // wait for strata 0..kz-1, then C += acc
        if (tid == 0) {
            while (atomicAdd(&g_cnt[tile], 0u) < (unsigned)kz) __nanosleep(64);
        }
        __syncthreads();
        __threadfence();
#pragma unroll
        for (int mt = 0; mt < 4; mt++) {
            int row0 = bm + warp_m * 64 + mt * 16 + (lane >> 2);
#pragma unroll
            for (int nt = 0; nt < 4; nt++) {
                int col = bn + warp_n * 32 + nt * 8 + (lane & 3) * 2;
                float* p0 = C + (size_t)row0 * OUTF + col;
                float* p1 = C + (size_t)(row0 + 8) * OUTF + col;
                float2 o0 = __ldcg((const float2*)p0);
                float2 o1 = __ldcg((const float2*)p1);
                o0.x += acc[mt][nt][0]; o0.y += acc[mt][nt][1];
                o1.x += acc[mt][nt][2]; o1.y += acc[mt][nt][3];
                *(float2*)p0 = o0;
                *(float2*)p1 = o1;
            }
        }
        __threadfence();
        __syncthreads();
        if (tid == 0) atomicAdd(&g_cnt[tile], 1u);
    }
}

// ===========================================================================
extern "C" void kernel_launch(void* const* d_in, const int* in_sizes, int n_in,
                              void* d_out, int out_size) {
    const float* x    = (const float*)d_in[0];   // [4096,1024]
    const float* bw   = (const float*)d_in[1];   // [1024,1024]
    const float* bias = (const float*)d_in[2];   // [1024]
    const float* sw   = (const float*)d_in[3];   // [1024,1024,8]
    float* out = (float*)d_out;                  // [4096,1024]

    static bool attr_set = false;
    if (!attr_set) {
        cudaFuncSetAttribute(gemm_kernel,
                             cudaFuncAttributeMaxDynamicSharedMemorySize, SMEM_TOTAL);
        attr_set = true;
    }

    reset_cnt_kernel<<<1, 256>>>();
    build_A_kernel<<<(NMAT * INF + 255) / 256, 256>>>(x);
    pack_W_kernel<<<(OUTF * INF + 255) / 256, 256>>>(bw, sw);

    dim3 grid(OUTF / BN, NMAT / BM, SPLITK);   // (8, 32, 4) = 1024 CTAs
    gemm_kernel<<<grid, 256, SMEM_TOTAL>>>(bias, out);
}